// round 15
// baseline (speedup 1.0000x reference)
#include <cuda_runtime.h>
#include <cuda_fp16.h>
#include <cstdint>
#include <math.h>

// ---------------- problem constants ----------------
constexpr int kN    = 8192;
constexpr int kC0   = 64;
constexpr int kC1   = 32;
constexpr int kP0   = kC0*(kC0+1)/2;      // 2080
constexpr int kP1   = kC1*(kC1+1)/2;      // 528
constexpr int kA1   = kC1*(kC1-1)/2;      // 496
constexpr int kM0   = kC0 + kP0 + kP1;    // 2672
constexpr int kM1   = kC1 + kC0*kC1;      // 2080
constexpr int kG    = kM0 + kM1 + kA1 + kP1; // 5776
constexpr int kOUTW = 64 + 32*3 + 16*3 + 16*5; // 288

__device__ constexpr float kRS2 = 0.70710678118654752f;
__device__ constexpr float kRS3 = 0.57735026918962576f;
__device__ constexpr float kS6  = 0.40824829046386302f;

// ---------------- scratch (static device globals; no allocation) ----------------
__device__ float  d_f0t[(size_t)kN*kM0];   // fp32 (skinny path)
__device__ __half d_f0h[(size_t)kN*kM0];   // fp16 (GEMM1 A)
__device__ __half d_h  [(size_t)kN*kM0];   // fp16 silu output (GEMM2 A)
__device__ __half d_g  [(size_t)kN*kG];    // fp16 gates
__device__ float  d_f1 [3][(size_t)kN*kM1];
__device__ float  d_f1e[3][(size_t)kN*kA1];
__device__ float  d_f2 [5][(size_t)kN*kP1];
__device__ __half d_w1t[(size_t)kM0*kM0];  // [N][K] K-major fp16
__device__ __half d_w2t[(size_t)kG*kM0];
__device__ int2   t_iu0[kP0];
__device__ float  t_c0 [kP0];
__device__ int2   t_iu1[kP1];
__device__ float  t_c1 [kP1];
__device__ int2   t_il [kA1];

// ---------------- PTX helpers ----------------
__device__ __forceinline__ uint32_t smem_u32(const void* p) {
    uint32_t a;
    asm("{ .reg .u64 t; cvta.to.shared.u64 t, %1; cvt.u32.u64 %0, t; }" : "=r"(a) : "l"(p));
    return a;
}
__device__ __forceinline__ void cp16(uint32_t dst, const void* src, bool pred) {
    int sz = pred ? 16 : 0;
    asm volatile("cp.async.cg.shared.global [%0], [%1], 16, %2;"
                 :: "r"(dst), "l"(src), "r"(sz) : "memory");
}
__device__ __forceinline__ void cp_commit() {
    asm volatile("cp.async.commit_group;" ::: "memory");
}
template<int NG>
__device__ __forceinline__ void cp_wait() {
    asm volatile("cp.async.wait_group %0;" :: "n"(NG) : "memory");
}
__device__ __forceinline__ void ldm_x4(uint32_t* r, uint32_t addr) {
    asm volatile("ldmatrix.sync.aligned.m8n8.x4.shared.b16 {%0,%1,%2,%3}, [%4];"
                 : "=r"(r[0]), "=r"(r[1]), "=r"(r[2]), "=r"(r[3]) : "r"(addr));
}
__device__ __forceinline__ void mma_f16(float* c, const uint32_t* a, const uint32_t* b) {
    asm volatile("mma.sync.aligned.m16n8k16.row.col.f32.f16.f16.f32 "
                 "{%0,%1,%2,%3}, {%4,%5,%6,%7}, {%8,%9}, {%0,%1,%2,%3};"
                 : "+f"(c[0]), "+f"(c[1]), "+f"(c[2]), "+f"(c[3])
                 : "r"(a[0]), "r"(a[1]), "r"(a[2]), "r"(a[3]), "r"(b[0]), "r"(b[1]));
}
__device__ __forceinline__ float tf32_round(float x) {
    uint32_t u;
    asm("cvt.rna.tf32.f32 %0, %1;" : "=r"(u) : "f"(x));
    return __uint_as_float(u);
}

// ---------------- triu decode (table init only) ----------------
__device__ __forceinline__ int2 triu_decode(int p, int C, int k)
{
    int Cm = C - k;
    float t = 2.0f*Cm + 1.0f;
    int a = (int)((t - sqrtf(t*t - 8.0f*(float)p)) * 0.5f);
    if (a < 0) a = 0;
    if (a > Cm-1) a = Cm-1;
    while (a > 0 && a*Cm - (a*(a-1))/2 > p) --a;
    while ((a+1)*Cm - ((a+1)*a)/2 <= p) ++a;
    int b = a + k + (p - (a*Cm - (a*(a-1))/2));
    return make_int2(a, b);
}

__global__ __launch_bounds__(256)
void init_tables()
{
    int i = blockIdx.x*256 + threadIdx.x;
    if (i < kP0) {
        int2 ab = triu_decode(i, kC0, 0);
        t_iu0[i] = ab;
        t_c0[i]  = (ab.x == ab.y) ? kRS2 : 1.0f;
    }
    if (i < kP1) {
        int2 ab = triu_decode(i, kC1, 0);
        t_iu1[i] = ab;
        t_c1[i]  = (ab.x == ab.y) ? kRS2 : 1.0f;
    }
    if (i < kA1) t_il[i] = triu_decode(i, kC1, 1);
}

// ---------------- stage 0: weight transpose + fp16 convert ----------------
__global__ __launch_bounds__(256)
void prep_weight(const float* __restrict__ W, __half* __restrict__ T, int K, int N)
{
    __shared__ float tile[32][33];
    int kb = blockIdx.y*32, nb = blockIdx.x*32;
    int tx = threadIdx.x & 31, ty = threadIdx.x >> 5;
    for (int i = ty; i < 32; i += 8) {
        int k = kb + i, n = nb + tx;
        tile[i][tx] = (k < K && n < N) ? W[(size_t)k*N + n] : 0.f;
    }
    __syncthreads();
    for (int i = ty; i < 32; i += 8) {
        int n = nb + i, k = kb + tx;
        if (n < N && k < K)
            T[(size_t)n*K + k] = __float2half(tile[tx][i]);
    }
}

// ---------------- stage 1: feature construction (table-driven) ----------------
__global__ __launch_bounds__(256)
void build_features(const float* __restrict__ xs, const float* __restrict__ xv)
{
    const int n = blockIdx.x;
    __shared__ float s[kC0];
    __shared__ float v[kC1][3];
    const int t = threadIdx.x;
    if (t < kC0) s[t] = xs[(size_t)n*kC0 + t];
    if (t >= 128 && t < 128 + kC1*3) ((float*)v)[t-128] = xv[(size_t)n*kC1*3 + (t-128)];
    __syncthreads();

    float*  f0t = d_f0t + (size_t)n*kM0;
    __half* f0h = d_f0h + (size_t)n*kM0;

    if (t < kC0) { float x = s[t]; f0t[t] = x; f0h[t] = __float2half(x); }
    for (int p = t; p < kP0; p += 256) {
        int2 ab = t_iu0[p];
        float x = s[ab.x]*s[ab.y]*t_c0[p];
        f0t[kC0 + p] = x;
        f0h[kC0 + p] = __float2half(x);
    }
    for (int p = t; p < kP1; p += 256) {
        int2 ab = t_iu1[p];
        float x = (v[ab.x][0]*v[ab.y][0] + v[ab.x][1]*v[ab.y][1] + v[ab.x][2]*v[ab.y][2])
                * t_c1[p] * kRS3;
        f0t[kC0 + kP0 + p] = x;
        f0h[kC0 + kP0 + p] = __float2half(x);
    }
    for (int c = t; c < kM1; c += 256) {
        float e0, e1, e2;
        if (c < kC1) { e0 = v[c][0]; e1 = v[c][1]; e2 = v[c][2]; }
        else {
            int cc = (c - kC1) >> 5;
            int vv = (c - kC1) & 31;
            float sc = s[cc];
            e0 = sc*v[vv][0]; e1 = sc*v[vv][1]; e2 = sc*v[vv][2];
        }
        size_t idx = (size_t)n*kM1 + c;
        d_f1[0][idx] = e0; d_f1[1][idx] = e1; d_f1[2][idx] = e2;
    }
    for (int p = t; p < kA1; p += 256) {
        int2 ab = t_il[p];
        float ux = v[ab.x][0], uy = v[ab.x][1], uz = v[ab.x][2];
        float wx = v[ab.y][0], wy = v[ab.y][1], wz = v[ab.y][2];
        size_t idx = (size_t)n*kA1 + p;
        d_f1e[0][idx] = (uy*wz - uz*wy) * kRS2;
        d_f1e[1][idx] = (uz*wx - ux*wz) * kRS2;
        d_f1e[2][idx] = (ux*wy - uy*wx) * kRS2;
    }
    for (int p = t; p < kP1; p += 256) {
        int2 ab = t_iu1[p];
        float c = t_c1[p];
        float ax = v[ab.x][0], ay = v[ab.x][1], az = v[ab.x][2];
        float bx = v[ab.y][0], by = v[ab.y][1], bz = v[ab.y][2];
        size_t idx = (size_t)n*kP1 + p;
        d_f2[0][idx] = kRS2*(ax*by + ay*bx)*c;
        d_f2[1][idx] = kRS2*(ay*bz + az*by)*c;
        d_f2[2][idx] = kRS2*(ax*bz + az*bx)*c;
        d_f2[3][idx] = kRS2*(ax*bx - ay*by)*c;
        d_f2[4][idx] = kS6*(-ax*bx - ay*by + 2.0f*az*bz)*c;
    }
}

// ---- fp16 HMMA GEMM: 128x128 tile, 256 thr, 2 CTAs/SM, BK=32 halves, 3-stage ----
constexpr int kHRowStride  = 80;                    // 64B data + 16B pad
constexpr int kHTileBytes  = 128 * kHRowStride;     // 10240
constexpr int kHBufBytes   = 2 * kHTileBytes;       // 20480
constexpr int kHStages     = 3;
constexpr int kHGemmSmem   = kHStages * kHBufBytes; // 61440

template<bool SILU>
__global__ __launch_bounds__(256, 2)
void hmma_gemm(const __half* __restrict__ A, const __half* __restrict__ B,
               __half* __restrict__ Ch, int K, int Nglob)
{
    extern __shared__ char smem[];
    const uint32_t sbase = smem_u32(smem);
    const int tid  = threadIdx.x;
    const int wid  = tid >> 5, lane = tid & 31;
    const int m0   = blockIdx.y * 128;
    const int n0   = blockIdx.x * 128;
    const int wm   = (wid & 1) * 64;
    const int wn   = (wid >> 1) * 32;

    float acc[4][4][4];
    #pragma unroll
    for (int i = 0; i < 4; i++)
        #pragma unroll
        for (int j = 0; j < 4; j++)
            #pragma unroll
            for (int q = 0; q < 4; q++) acc[i][j][q] = 0.0f;

    const int nChunks = (K + 31) / 32;

    auto load_chunk = [&](int c) {
        const uint32_t db = sbase + (uint32_t)(c % kHStages) * kHBufBytes;
        const int k0 = c * 32;
        #pragma unroll
        for (int t = 0; t < 4; t++) {
            int idx = t * 256 + tid;
            int kc  = idx & 3;
            int gk  = k0 + kc * 8;
            bool kok = gk < K;
            int row = (idx >> 2) & 127;
            const __half* src;
            uint32_t dst;
            bool ok;
            if (idx < 512) {
                dst = db + (uint32_t)row * kHRowStride + kc * 16;
                src = A + (size_t)(m0 + row) * K + (kok ? gk : 0);
                ok  = kok;
            } else {
                dst = db + (uint32_t)kHTileBytes + (uint32_t)row * kHRowStride + kc * 16;
                int gn = n0 + row;
                bool nok = gn < Nglob;
                src = B + (size_t)(nok ? gn : 0) * K + (kok ? gk : 0);
                ok  = kok && nok;
            }
            cp16(dst, src, ok);
        }
        cp_commit();
    };

    load_chunk(0);
    load_chunk(1);

    for (int c = 0; c < nChunks; c++) {
        if (c + 1 < nChunks) cp_wait<1>(); else cp_wait<0>();
        __syncthreads();
        if (c + 2 < nChunks) load_chunk(c + 2);

        const uint32_t db = sbase + (uint32_t)(c % kHStages) * kHBufBytes;
        const uint32_t aT = db;
        const uint32_t bT = db + kHTileBytes;

        #pragma unroll
        for (int ks = 0; ks < 2; ks++) {
            uint32_t af[4][4], bf[4][2];
            const int arow = wm + (lane & 15);
            const int acol = ks * 32 + (lane >> 4) * 16;
            #pragma unroll
            for (int mt = 0; mt < 4; mt++) {
                uint32_t off = (uint32_t)(arow + mt*16) * kHRowStride + acol;
                ldm_x4(af[mt], aT + off);
            }
            const int bg  = lane >> 3;
            const int br  = lane & 7;
            const int bnt = bg >> 1;
            const int bkh = (bg & 1) * 16;
            #pragma unroll
            for (int np = 0; np < 2; np++) {
                uint32_t off = (uint32_t)(wn + (np*2 + bnt)*8 + br) * kHRowStride
                             + ks*32 + bkh;
                ldm_x4(&bf[np*2][0], bT + off);
            }
            #pragma unroll
            for (int mt = 0; mt < 4; mt++)
                #pragma unroll
                for (int nt = 0; nt < 4; nt++)
                    mma_f16(acc[mt][nt], af[mt], bf[nt]);
        }
    }

    #pragma unroll
    for (int mt = 0; mt < 4; mt++) {
        #pragma unroll
        for (int nt = 0; nt < 4; nt++) {
            int row = m0 + wm + mt*16 + (lane >> 2);
            int col = n0 + wn + nt*8 + (lane & 3) * 2;
            #pragma unroll
            for (int half = 0; half < 2; half++) {
                int r = row + half * 8;
                float v0 = acc[mt][nt][half*2 + 0];
                float v1 = acc[mt][nt][half*2 + 1];
                if (col < Nglob) {
                    size_t o = (size_t)r * Nglob + col;
                    if (SILU) {
                        v0 = v0 / (1.0f + __expf(-v0));
                        v1 = v1 / (1.0f + __expf(-v1));
                    }
                    Ch[o]   = __float2half(v0);
                    Ch[o+1] = __float2half(v1);
                }
            }
        }
    }
}

// ---- stage 5: ALL output families in ONE launch (fp16 MMA) ----
// 832 blocks: [0,128) o0 | [128,320) o1 | [320,512) o1e | [512,832) o2.
constexpr int kSkRS   = 80;                 // 64B data + 16B pad
constexpr int kSkA    = 128 * kSkRS;        // 10240
constexpr int kSkB    = 32  * kSkRS;        // 2560
constexpr int kSkBuf  = kSkA + kSkB;        // 12800

__global__ __launch_bounds__(256)
void skinny_all(const __half* __restrict__ g,
                const float* __restrict__ w0,  const float* __restrict__ w1o,
                const float* __restrict__ w1e, const float* __restrict__ w2e,
                float* __restrict__ out)
{
    __shared__ char smem[2 * kSkBuf];
    const int tid  = threadIdx.x;
    const int wid  = tid >> 5, lane = tid & 31;
    const int b    = blockIdx.x;

    const float* A; const float* Wp;
    int K, gOff, ldw, colOff = 0, outBase, outStride, comp = 0, OC, rb;
    if (b < 128) {
        rb = b & 63; colOff = (b >> 6) * 32;
        A = d_f0t; K = kM0; gOff = 0; Wp = w0; ldw = 64;
        outBase = 0; outStride = 1; OC = 32;
    } else if (b < 320) {
        int t = b - 128; comp = t >> 6; rb = t & 63;
        A = d_f1[comp]; K = kM1; gOff = kM0; Wp = w1o; ldw = 32;
        outBase = 64; outStride = 3; OC = 32;
    } else if (b < 512) {
        int t = b - 320; comp = t >> 6; rb = t & 63;
        A = d_f1e[comp]; K = kA1; gOff = kM0 + kM1; Wp = w1e; ldw = 16;
        outBase = 160; outStride = 3; OC = 16;
    } else {
        int t = b - 512; comp = t >> 6; rb = t & 63;
        A = d_f2[comp]; K = kP1; gOff = kM0 + kM1 + kA1; Wp = w2e; ldw = 16;
        outBase = 208; outStride = 5; OC = 16;
    }
    const int n0 = rb * 128;
    const int wm = wid * 16;
    const int ocDiv8  = OC >> 3;
    const int ocDiv16 = OC >> 4;

    float acc[4][4];
    #pragma unroll
    for (int j = 0; j < 4; j++)
        #pragma unroll
        for (int q = 0; q < 4; q++) acc[j][q] = 0.0f;

    const int nChunks = (K + 31) / 32;

    float4 aP[4];
    uint2  gP[4];     // 4 halves each
    float  wP[4];

    auto load_regs = [&](int c) {
        const int k0 = c * 32;
        #pragma unroll
        for (int j = 0; j < 4; j++) {
            int i  = j * 256 + tid;      // 0..1023
            int r  = i >> 3;             // 0..127
            int kq = i & 7;              // 8 groups of 4 elems per 32-wide row
            int gk = k0 + kq * 4;
            if (gk < K) {                // K % 4 == 0 for all families
                aP[j] = *reinterpret_cast<const float4*>(A + (size_t)(n0 + r)*K + gk);
                gP[j] = *reinterpret_cast<const uint2*>(g + (size_t)(n0 + r)*kG + gOff + gk);
            } else {
                aP[j] = make_float4(0.f, 0.f, 0.f, 0.f);
                gP[j] = make_uint2(0x3C003C00u, 0x3C003C00u);   // half(1.0) x4
            }
        }
        #pragma unroll
        for (int j = 0; j < 4; j++) {
            int i = j * 256 + tid;
            wP[j] = 0.f;
            if (i < OC * 32) {
                int k = i / OC, o = i % OC;
                if (k0 + k < K)
                    wP[j] = Wp[(size_t)(k0 + k)*ldw + colOff + o];
            }
        }
    };

    auto store_smem = [&](int buf) {
        char* base = smem + buf * kSkBuf;
        #pragma unroll
        for (int j = 0; j < 4; j++) {
            int i  = j * 256 + tid;
            int r  = i >> 3;
            int kq = i & 7;
            __half2 g01 = *reinterpret_cast<const __half2*>(&gP[j].x);
            __half2 g23 = *reinterpret_cast<const __half2*>(&gP[j].y);
            float2 gf01 = __half22float2(g01);
            float2 gf23 = __half22float2(g23);
            __half2 p01 = __floats2half2_rn(aP[j].x * gf01.x, aP[j].y * gf01.y);
            __half2 p23 = __floats2half2_rn(aP[j].z * gf23.x, aP[j].w * gf23.y);
            uint2 pk;
            pk.x = *reinterpret_cast<uint32_t*>(&p01);
            pk.y = *reinterpret_cast<uint32_t*>(&p23);
            *reinterpret_cast<uint2*>(base + r*kSkRS + kq*8) = pk;
        }
        #pragma unroll
        for (int j = 0; j < 4; j++) {
            int i = j * 256 + tid;
            if (i < OC * 32) {
                int k = i / OC, o = i % OC;
                *reinterpret_cast<__half*>(base + kSkA + o*kSkRS + k*2) = __float2half(wP[j]);
            }
        }
    };

    load_regs(0);

    for (int c = 0; c < nChunks; c++) {
        const int buf = c & 1;
        store_smem(buf);
        __syncthreads();
        if (c + 1 < nChunks) load_regs(c + 1);

        const uint32_t aT = smem_u32(smem) + buf * kSkBuf;
        const uint32_t bT = aT + kSkA;

        #pragma unroll
        for (int ks = 0; ks < 2; ks++) {          // two k16 steps per 32-chunk
            uint32_t af[4], bf[4][2];
            const int arow = wm + (lane & 15);
            const int acol = ks * 32 + (lane >> 4) * 16;
            ldm_x4(af, aT + (uint32_t)arow * kSkRS + acol);
            const int bg  = lane >> 3;
            const int br  = lane & 7;
            const int bnt = bg >> 1;
            const int bkh = (bg & 1) * 16;
            #pragma unroll
            for (int np = 0; np < 2; np++) {
                if (np < ocDiv16) {
                    uint32_t off = (uint32_t)((np*2 + bnt)*8 + br) * kSkRS
                                 + ks*32 + bkh;
                    ldm_x4(&bf[np*2][0], bT + off);
                }
            }
            #pragma unroll
            for (int nt = 0; nt < 4; nt++)
                if (nt < ocDiv8)
                    mma_f16(acc[nt], af, bf[nt]);
        }
    }

    #pragma unroll
    for (int nt = 0; nt < 4; nt++) {
        if (nt < ocDiv8) {
            int row = n0 + wm + (lane >> 2);
            int oc  = colOff + nt*8 + (lane & 3) * 2;
            #pragma unroll
            for (int half = 0; half < 2; half++) {
                int r = row + half * 8;
                size_t o = (size_t)r * kOUTW + outBase + comp + (size_t)oc * outStride;
                out[o]             = acc[nt][half*2 + 0];
                out[o + outStride] = acc[nt][half*2 + 1];
            }
        }
    }
}

// ---------------- launch ----------------
extern "C" void kernel_launch(void* const* d_in, const int* in_sizes, int n_in,
                              void* d_out, int out_size)
{
    const float* xs  = (const float*)d_in[0];
    const float* xv  = (const float*)d_in[1];
    const float* w1  = (const float*)d_in[2];
    const float* w2  = (const float*)d_in[3];
    const float* w0  = (const float*)d_in[4];
    const float* w1o = (const float*)d_in[5];
    const float* w1e = (const float*)d_in[6];
    const float* w2e = (const float*)d_in[7];
    float* out = (float*)d_out;

    void *pf0h, *ph, *pg, *pw1t, *pw2t;
    cudaGetSymbolAddress(&pf0h, d_f0h);
    cudaGetSymbolAddress(&ph,   d_h);
    cudaGetSymbolAddress(&pg,   d_g);
    cudaGetSymbolAddress(&pw1t, d_w1t);
    cudaGetSymbolAddress(&pw2t, d_w2t);

    __half* f0hv = (__half*)pf0h;
    __half* hv   = (__half*)ph;
    __half* gv   = (__half*)pg;
    __half* w1tv = (__half*)pw1t;
    __half* w2tv = (__half*)pw2t;

    cudaFuncSetAttribute(hmma_gemm<true>,  cudaFuncAttributeMaxDynamicSharedMemorySize, kHGemmSmem);
    cudaFuncSetAttribute(hmma_gemm<false>, cudaFuncAttributeMaxDynamicSharedMemorySize, kHGemmSmem);

    // stage -1: pair tables
    init_tables<<<(kP0 + 255)/256, 256>>>();

    // stage 0: weight transpose + fp16 convert
    prep_weight<<<dim3((kM0+31)/32, (kM0+31)/32), 256>>>(w1, w1tv, kM0, kM0);
    prep_weight<<<dim3((kG +31)/32, (kM0+31)/32), 256>>>(w2, w2tv, kM0, kG);

    // stage 1: features (fp32 f0t + fp16 f0h)
    build_features<<<kN, 256>>>(xs, xv);

    // stage 2: h = fp16(silu(f0h @ W1))      [8192 x 2672]
    {
        dim3 grid((kM0 + 127)/128, kN/128);
        hmma_gemm<true><<<grid, 256, kHGemmSmem>>>(f0hv, w1tv, hv, kM0, kM0);
    }
    // stage 3: g = fp16(h @ W2)              [8192 x 5776]
    {
        dim3 grid((kG + 127)/128, kN/128);
        hmma_gemm<false><<<grid, 256, kHGemmSmem>>>(hv, w2tv, gv, kM0, kG);
    }

    // stage 5: all gated output GEMMs in one launch (fp16 MMA)
    skinny_all<<<832, 256>>>(gv, w0, w1o, w1e, w2e, out);
}

// round 16
// speedup vs baseline: 1.4516x; 1.4516x over previous
#include <cuda_runtime.h>
#include <cuda_fp16.h>
#include <cstdint>
#include <math.h>

// ---------------- problem constants ----------------
constexpr int kN    = 8192;
constexpr int kC0   = 64;
constexpr int kC1   = 32;
constexpr int kP0   = kC0*(kC0+1)/2;      // 2080
constexpr int kP1   = kC1*(kC1+1)/2;      // 528
constexpr int kA1   = kC1*(kC1-1)/2;      // 496
constexpr int kM0   = kC0 + kP0 + kP1;    // 2672
constexpr int kM1   = kC1 + kC0*kC1;      // 2080
constexpr int kG    = kM0 + kM1 + kA1 + kP1; // 5776
constexpr int kOUTW = 64 + 32*3 + 16*3 + 16*5; // 288

__device__ constexpr float kRS2 = 0.70710678118654752f;
__device__ constexpr float kRS3 = 0.57735026918962576f;
__device__ constexpr float kS6  = 0.40824829046386302f;

// ---------------- scratch (static device globals; no allocation) ----------------
__device__ __half d_f0h[(size_t)kN*kM0];   // fp16 f0 (GEMM1 A + skinny fam0)
__device__ __half d_h  [(size_t)kN*kM0];   // fp16 silu output (GEMM2 A)
__device__ float  d_g  [(size_t)kN*kG];    // fp32 gates
__device__ float  d_f1 [3][(size_t)kN*kM1];
__device__ float  d_f1e[3][(size_t)kN*kA1];
__device__ float  d_f2 [5][(size_t)kN*kP1];
__device__ __half d_w1t[(size_t)kM0*kM0];  // [N][K] K-major fp16
__device__ __half d_w2t[(size_t)kG*kM0];
__device__ int2   t_iu0[kP0];
__device__ float  t_c0 [kP0];
__device__ int2   t_iu1[kP1];
__device__ float  t_c1 [kP1];
__device__ int2   t_il [kA1];

// ---------------- PTX helpers ----------------
__device__ __forceinline__ uint32_t smem_u32(const void* p) {
    uint32_t a;
    asm("{ .reg .u64 t; cvta.to.shared.u64 t, %1; cvt.u32.u64 %0, t; }" : "=r"(a) : "l"(p));
    return a;
}
__device__ __forceinline__ void cp16(uint32_t dst, const void* src, bool pred) {
    int sz = pred ? 16 : 0;
    asm volatile("cp.async.cg.shared.global [%0], [%1], 16, %2;"
                 :: "r"(dst), "l"(src), "r"(sz) : "memory");
}
__device__ __forceinline__ void cp_commit() {
    asm volatile("cp.async.commit_group;" ::: "memory");
}
template<int NG>
__device__ __forceinline__ void cp_wait() {
    asm volatile("cp.async.wait_group %0;" :: "n"(NG) : "memory");
}
__device__ __forceinline__ void ldm_x4(uint32_t* r, uint32_t addr) {
    asm volatile("ldmatrix.sync.aligned.m8n8.x4.shared.b16 {%0,%1,%2,%3}, [%4];"
                 : "=r"(r[0]), "=r"(r[1]), "=r"(r[2]), "=r"(r[3]) : "r"(addr));
}
__device__ __forceinline__ void mma_f16(float* c, const uint32_t* a, const uint32_t* b) {
    asm volatile("mma.sync.aligned.m16n8k16.row.col.f32.f16.f16.f32 "
                 "{%0,%1,%2,%3}, {%4,%5,%6,%7}, {%8,%9}, {%0,%1,%2,%3};"
                 : "+f"(c[0]), "+f"(c[1]), "+f"(c[2]), "+f"(c[3])
                 : "r"(a[0]), "r"(a[1]), "r"(a[2]), "r"(a[3]), "r"(b[0]), "r"(b[1]));
}
__device__ __forceinline__ void mma_tf32(float* c, const uint32_t* a, const uint32_t* b) {
    asm volatile("mma.sync.aligned.m16n8k8.row.col.f32.tf32.tf32.f32 "
                 "{%0,%1,%2,%3}, {%4,%5,%6,%7}, {%8,%9}, {%0,%1,%2,%3};"
                 : "+f"(c[0]), "+f"(c[1]), "+f"(c[2]), "+f"(c[3])
                 : "r"(a[0]), "r"(a[1]), "r"(a[2]), "r"(a[3]), "r"(b[0]), "r"(b[1]));
}
__device__ __forceinline__ float tf32_round(float x) {
    uint32_t u;
    asm("cvt.rna.tf32.f32 %0, %1;" : "=r"(u) : "f"(x));
    return __uint_as_float(u);
}

// ---------------- triu decode (table init only) ----------------
__device__ __forceinline__ int2 triu_decode(int p, int C, int k)
{
    int Cm = C - k;
    float t = 2.0f*Cm + 1.0f;
    int a = (int)((t - sqrtf(t*t - 8.0f*(float)p)) * 0.5f);
    if (a < 0) a = 0;
    if (a > Cm-1) a = Cm-1;
    while (a > 0 && a*Cm - (a*(a-1))/2 > p) --a;
    while ((a+1)*Cm - ((a+1)*a)/2 <= p) ++a;
    int b = a + k + (p - (a*Cm - (a*(a-1))/2));
    return make_int2(a, b);
}

__global__ __launch_bounds__(256)
void init_tables()
{
    int i = blockIdx.x*256 + threadIdx.x;
    if (i < kP0) {
        int2 ab = triu_decode(i, kC0, 0);
        t_iu0[i] = ab;
        t_c0[i]  = (ab.x == ab.y) ? kRS2 : 1.0f;
    }
    if (i < kP1) {
        int2 ab = triu_decode(i, kC1, 0);
        t_iu1[i] = ab;
        t_c1[i]  = (ab.x == ab.y) ? kRS2 : 1.0f;
    }
    if (i < kA1) t_il[i] = triu_decode(i, kC1, 1);
}

// ---------------- stage 0: weight transpose + fp16 convert ----------------
__global__ __launch_bounds__(256)
void prep_weight(const float* __restrict__ W, __half* __restrict__ T, int K, int N)
{
    __shared__ float tile[32][33];
    int kb = blockIdx.y*32, nb = blockIdx.x*32;
    int tx = threadIdx.x & 31, ty = threadIdx.x >> 5;
    for (int i = ty; i < 32; i += 8) {
        int k = kb + i, n = nb + tx;
        tile[i][tx] = (k < K && n < N) ? W[(size_t)k*N + n] : 0.f;
    }
    __syncthreads();
    for (int i = ty; i < 32; i += 8) {
        int n = nb + i, k = kb + tx;
        if (n < N && k < K)
            T[(size_t)n*K + k] = __float2half(tile[tx][i]);
    }
}

// ---------------- stage 1: feature construction (table-driven) ----------------
__global__ __launch_bounds__(256)
void build_features(const float* __restrict__ xs, const float* __restrict__ xv)
{
    const int n = blockIdx.x;
    __shared__ float s[kC0];
    __shared__ float v[kC1][3];
    const int t = threadIdx.x;
    if (t < kC0) s[t] = xs[(size_t)n*kC0 + t];
    if (t >= 128 && t < 128 + kC1*3) ((float*)v)[t-128] = xv[(size_t)n*kC1*3 + (t-128)];
    __syncthreads();

    __half* f0h = d_f0h + (size_t)n*kM0;

    if (t < kC0) f0h[t] = __float2half(s[t]);
    for (int p = t; p < kP0; p += 256) {
        int2 ab = t_iu0[p];
        f0h[kC0 + p] = __float2half(s[ab.x]*s[ab.y]*t_c0[p]);
    }
    for (int p = t; p < kP1; p += 256) {
        int2 ab = t_iu1[p];
        float x = (v[ab.x][0]*v[ab.y][0] + v[ab.x][1]*v[ab.y][1] + v[ab.x][2]*v[ab.y][2])
                * t_c1[p] * kRS3;
        f0h[kC0 + kP0 + p] = __float2half(x);
    }
    for (int c = t; c < kM1; c += 256) {
        float e0, e1, e2;
        if (c < kC1) { e0 = v[c][0]; e1 = v[c][1]; e2 = v[c][2]; }
        else {
            int cc = (c - kC1) >> 5;
            int vv = (c - kC1) & 31;
            float sc = s[cc];
            e0 = sc*v[vv][0]; e1 = sc*v[vv][1]; e2 = sc*v[vv][2];
        }
        size_t idx = (size_t)n*kM1 + c;
        d_f1[0][idx] = e0; d_f1[1][idx] = e1; d_f1[2][idx] = e2;
    }
    for (int p = t; p < kA1; p += 256) {
        int2 ab = t_il[p];
        float ux = v[ab.x][0], uy = v[ab.x][1], uz = v[ab.x][2];
        float wx = v[ab.y][0], wy = v[ab.y][1], wz = v[ab.y][2];
        size_t idx = (size_t)n*kA1 + p;
        d_f1e[0][idx] = (uy*wz - uz*wy) * kRS2;
        d_f1e[1][idx] = (uz*wx - ux*wz) * kRS2;
        d_f1e[2][idx] = (ux*wy - uy*wx) * kRS2;
    }
    for (int p = t; p < kP1; p += 256) {
        int2 ab = t_iu1[p];
        float c = t_c1[p];
        float ax = v[ab.x][0], ay = v[ab.x][1], az = v[ab.x][2];
        float bx = v[ab.y][0], by = v[ab.y][1], bz = v[ab.y][2];
        size_t idx = (size_t)n*kP1 + p;
        d_f2[0][idx] = kRS2*(ax*by + ay*bx)*c;
        d_f2[1][idx] = kRS2*(ay*bz + az*by)*c;
        d_f2[2][idx] = kRS2*(ax*bz + az*bx)*c;
        d_f2[3][idx] = kRS2*(ax*bx - ay*by)*c;
        d_f2[4][idx] = kS6*(-ax*bx - ay*by + 2.0f*az*bz)*c;
    }
}

// ---- fp16 HMMA GEMM: 128x128 tile, 256 thr, 2 CTAs/SM, BK=32 halves, 3-stage ----
constexpr int kHRowStride  = 80;                    // 64B data + 16B pad
constexpr int kHTileBytes  = 128 * kHRowStride;     // 10240
constexpr int kHBufBytes   = 2 * kHTileBytes;       // 20480
constexpr int kHStages     = 3;
constexpr int kHGemmSmem   = kHStages * kHBufBytes; // 61440

template<bool SILU>
__global__ __launch_bounds__(256, 2)
void hmma_gemm(const __half* __restrict__ A, const __half* __restrict__ B,
               float* __restrict__ Cf, __half* __restrict__ Ch, int K, int Nglob)
{
    extern __shared__ char smem[];
    const uint32_t sbase = smem_u32(smem);
    const int tid  = threadIdx.x;
    const int wid  = tid >> 5, lane = tid & 31;
    const int m0   = blockIdx.y * 128;
    const int n0   = blockIdx.x * 128;
    const int wm   = (wid & 1) * 64;
    const int wn   = (wid >> 1) * 32;

    float acc[4][4][4];
    #pragma unroll
    for (int i = 0; i < 4; i++)
        #pragma unroll
        for (int j = 0; j < 4; j++)
            #pragma unroll
            for (int q = 0; q < 4; q++) acc[i][j][q] = 0.0f;

    const int nChunks = (K + 31) / 32;

    auto load_chunk = [&](int c) {
        const uint32_t db = sbase + (uint32_t)(c % kHStages) * kHBufBytes;
        const int k0 = c * 32;
        #pragma unroll
        for (int t = 0; t < 4; t++) {
            int idx = t * 256 + tid;
            int kc  = idx & 3;
            int gk  = k0 + kc * 8;
            bool kok = gk < K;
            int row = (idx >> 2) & 127;
            const __half* src;
            uint32_t dst;
            bool ok;
            if (idx < 512) {
                dst = db + (uint32_t)row * kHRowStride + kc * 16;
                src = A + (size_t)(m0 + row) * K + (kok ? gk : 0);
                ok  = kok;
            } else {
                dst = db + (uint32_t)kHTileBytes + (uint32_t)row * kHRowStride + kc * 16;
                int gn = n0 + row;
                bool nok = gn < Nglob;
                src = B + (size_t)(nok ? gn : 0) * K + (kok ? gk : 0);
                ok  = kok && nok;
            }
            cp16(dst, src, ok);
        }
        cp_commit();
    };

    load_chunk(0);
    load_chunk(1);

    for (int c = 0; c < nChunks; c++) {
        if (c + 1 < nChunks) cp_wait<1>(); else cp_wait<0>();
        __syncthreads();
        if (c + 2 < nChunks) load_chunk(c + 2);

        const uint32_t db = sbase + (uint32_t)(c % kHStages) * kHBufBytes;
        const uint32_t aT = db;
        const uint32_t bT = db + kHTileBytes;

        #pragma unroll
        for (int ks = 0; ks < 2; ks++) {
            uint32_t af[4][4], bf[4][2];
            const int arow = wm + (lane & 15);
            const int acol = ks * 32 + (lane >> 4) * 16;
            #pragma unroll
            for (int mt = 0; mt < 4; mt++) {
                uint32_t off = (uint32_t)(arow + mt*16) * kHRowStride + acol;
                ldm_x4(af[mt], aT + off);
            }
            const int bg  = lane >> 3;
            const int br  = lane & 7;
            const int bnt = bg >> 1;
            const int bkh = (bg & 1) * 16;
            #pragma unroll
            for (int np = 0; np < 2; np++) {
                uint32_t off = (uint32_t)(wn + (np*2 + bnt)*8 + br) * kHRowStride
                             + ks*32 + bkh;
                ldm_x4(&bf[np*2][0], bT + off);
            }
            #pragma unroll
            for (int mt = 0; mt < 4; mt++)
                #pragma unroll
                for (int nt = 0; nt < 4; nt++)
                    mma_f16(acc[mt][nt], af[mt], bf[nt]);
        }
    }

    #pragma unroll
    for (int mt = 0; mt < 4; mt++) {
        #pragma unroll
        for (int nt = 0; nt < 4; nt++) {
            int row = m0 + wm + mt*16 + (lane >> 2);
            int col = n0 + wn + nt*8 + (lane & 3) * 2;
            #pragma unroll
            for (int half = 0; half < 2; half++) {
                int r = row + half * 8;
                float v0 = acc[mt][nt][half*2 + 0];
                float v1 = acc[mt][nt][half*2 + 1];
                if (col < Nglob) {
                    size_t o = (size_t)r * Nglob + col;
                    if (SILU) {
                        v0 = v0 / (1.0f + __expf(-v0));
                        v1 = v1 / (1.0f + __expf(-v1));
                        Ch[o]   = __float2half(v0);
                        Ch[o+1] = __float2half(v1);
                    } else {
                        Cf[o]   = v0;
                        Cf[o+1] = v1;
                    }
                }
            }
        }
    }
}

// ---- stage 5: ALL output families in ONE launch (tf32 MMA, fp32 g — R14-proven) ----
constexpr int kSkRowStride = 144;
constexpr int kSkASize     = 128 * kSkRowStride;    // 18432
constexpr int kSkBSize     = 32  * kSkRowStride;    // 4608
constexpr int kSkBuf       = kSkASize + kSkBSize;   // 23040

__global__ __launch_bounds__(256)
void skinny_all(const float* __restrict__ g,
                const float* __restrict__ w0,  const float* __restrict__ w1o,
                const float* __restrict__ w1e, const float* __restrict__ w2e,
                float* __restrict__ out)
{
    __shared__ char smem[2 * kSkBuf];
    const int tid  = threadIdx.x;
    const int wid  = tid >> 5, lane = tid & 31;
    const int b    = blockIdx.x;

    const float* A = nullptr; const float* Wp;
    bool fam0 = false;
    int K, gOff, ldw, colOff = 0, outBase, outStride, comp = 0, OC, rb;
    if (b < 128) {
        fam0 = true;
        rb = b & 63; colOff = (b >> 6) * 32;
        K = kM0; gOff = 0; Wp = w0; ldw = 64;
        outBase = 0; outStride = 1; OC = 32;
    } else if (b < 320) {
        int t = b - 128; comp = t >> 6; rb = t & 63;
        A = d_f1[comp]; K = kM1; gOff = kM0; Wp = w1o; ldw = 32;
        outBase = 64; outStride = 3; OC = 32;
    } else if (b < 512) {
        int t = b - 320; comp = t >> 6; rb = t & 63;
        A = d_f1e[comp]; K = kA1; gOff = kM0 + kM1; Wp = w1e; ldw = 16;
        outBase = 160; outStride = 3; OC = 16;
    } else {
        int t = b - 512; comp = t >> 6; rb = t & 63;
        A = d_f2[comp]; K = kP1; gOff = kM0 + kM1 + kA1; Wp = w2e; ldw = 16;
        outBase = 208; outStride = 5; OC = 16;
    }
    const int n0 = rb * 128;
    const int wm = wid * 16;
    const int ocDiv8  = OC >> 3;
    const int ocDiv16 = OC >> 4;

    float acc[4][4];
    #pragma unroll
    for (int j = 0; j < 4; j++)
        #pragma unroll
        for (int q = 0; q < 4; q++) acc[j][q] = 0.0f;

    const int nChunks = (K + 31) / 32;

    float4 aP[4], gP[4];
    float  wP[4];

    auto load_regs = [&](int c) {
        const int k0 = c * 32;
        #pragma unroll
        for (int j = 0; j < 4; j++) {
            int i  = j * 256 + tid;
            int r  = i >> 3;
            int kq = i & 7;
            int gk = k0 + kq * 4;
            if (gk < K) {
                if (fam0) {
                    // fp16 f0 -> fp32 (same 10-bit mantissa as tf32: error-neutral)
                    uint2 h4 = *reinterpret_cast<const uint2*>(
                        d_f0h + (size_t)(n0 + r)*kM0 + gk);
                    __half2 h01 = *reinterpret_cast<const __half2*>(&h4.x);
                    __half2 h23 = *reinterpret_cast<const __half2*>(&h4.y);
                    float2 f01 = __half22float2(h01);
                    float2 f23 = __half22float2(h23);
                    aP[j] = make_float4(f01.x, f01.y, f23.x, f23.y);
                } else {
                    aP[j] = *reinterpret_cast<const float4*>(A + (size_t)(n0 + r)*K + gk);
                }
                gP[j] = *reinterpret_cast<const float4*>(g + (size_t)(n0 + r)*kG + gOff + gk);
            } else {
                aP[j] = make_float4(0.f, 0.f, 0.f, 0.f);
                gP[j] = make_float4(1.f, 1.f, 1.f, 1.f);
            }
        }
        #pragma unroll
        for (int j = 0; j < 4; j++) {
            int i = j * 256 + tid;
            wP[j] = 0.f;
            if (i < OC * 32) {
                int k = i / OC, o = i % OC;
                if (k0 + k < K)
                    wP[j] = Wp[(size_t)(k0 + k)*ldw + colOff + o];
            }
        }
    };

    auto store_smem = [&](int buf) {
        char* base = smem + buf * kSkBuf;
        #pragma unroll
        for (int j = 0; j < 4; j++) {
            int i  = j * 256 + tid;
            int r  = i >> 3;
            int kq = i & 7;
            float4 a4;
            a4.x = tf32_round(aP[j].x * gP[j].x);
            a4.y = tf32_round(aP[j].y * gP[j].y);
            a4.z = tf32_round(aP[j].z * gP[j].z);
            a4.w = tf32_round(aP[j].w * gP[j].w);
            *reinterpret_cast<float4*>(base + r*kSkRowStride + kq*16) = a4;
        }
        #pragma unroll
        for (int j = 0; j < 4; j++) {
            int i = j * 256 + tid;
            if (i < OC * 32) {
                int k = i / OC, o = i % OC;
                *reinterpret_cast<float*>(base + kSkASize + o*kSkRowStride + k*4) = wP[j];
            }
        }
    };

    load_regs(0);

    for (int c = 0; c < nChunks; c++) {
        const int buf = c & 1;
        store_smem(buf);
        __syncthreads();
        if (c + 1 < nChunks) load_regs(c + 1);

        const uint32_t aT = smem_u32(smem) + buf * kSkBuf;
        const uint32_t bT = aT + kSkASize;

        #pragma unroll
        for (int s = 0; s < 4; s++) {
            uint32_t af[4], bf[4][2];
            const int arow = wm + (lane & 15);
            const int acol = s * 32 + (lane >> 4) * 16;
            ldm_x4(af, aT + (uint32_t)arow * kSkRowStride + acol);
            const int bg  = lane >> 3;
            const int br  = lane & 7;
            const int bnt = bg >> 1;
            const int bkh = (bg & 1) * 16;
            #pragma unroll
            for (int np = 0; np < 2; np++) {
                if (np < ocDiv16) {
                    uint32_t off = (uint32_t)((np*2 + bnt)*8 + br) * kSkRowStride
                                 + s*32 + bkh;
                    ldm_x4(&bf[np*2][0], bT + off);
                }
            }
            #pragma unroll
            for (int nt = 0; nt < 4; nt++)
                if (nt < ocDiv8)
                    mma_tf32(acc[nt], af, bf[nt]);
        }
    }

    #pragma unroll
    for (int nt = 0; nt < 4; nt++) {
        if (nt < ocDiv8) {
            int row = n0 + wm + (lane >> 2);
            int oc  = colOff + nt*8 + (lane & 3) * 2;
            #pragma unroll
            for (int half = 0; half < 2; half++) {
                int r = row + half * 8;
                size_t o = (size_t)r * kOUTW + outBase + comp + (size_t)oc * outStride;
                out[o]             = acc[nt][half*2 + 0];
                out[o + outStride] = acc[nt][half*2 + 1];
            }
        }
    }
}

// ---------------- launch ----------------
extern "C" void kernel_launch(void* const* d_in, const int* in_sizes, int n_in,
                              void* d_out, int out_size)
{
    const float* xs  = (const float*)d_in[0];
    const float* xv  = (const float*)d_in[1];
    const float* w1  = (const float*)d_in[2];
    const float* w2  = (const float*)d_in[3];
    const float* w0  = (const float*)d_in[4];
    const float* w1o = (const float*)d_in[5];
    const float* w1e = (const float*)d_in[6];
    const float* w2e = (const float*)d_in[7];
    float* out = (float*)d_out;

    void *pf0h, *ph, *pg, *pw1t, *pw2t;
    cudaGetSymbolAddress(&pf0h, d_f0h);
    cudaGetSymbolAddress(&ph,   d_h);
    cudaGetSymbolAddress(&pg,   d_g);
    cudaGetSymbolAddress(&pw1t, d_w1t);
    cudaGetSymbolAddress(&pw2t, d_w2t);

    __half* f0hv = (__half*)pf0h;
    __half* hv   = (__half*)ph;
    float*  gv   = (float*)pg;
    __half* w1tv = (__half*)pw1t;
    __half* w2tv = (__half*)pw2t;

    cudaFuncSetAttribute(hmma_gemm<true>,  cudaFuncAttributeMaxDynamicSharedMemorySize, kHGemmSmem);
    cudaFuncSetAttribute(hmma_gemm<false>, cudaFuncAttributeMaxDynamicSharedMemorySize, kHGemmSmem);

    // stage -1: pair tables
    init_tables<<<(kP0 + 255)/256, 256>>>();

    // stage 0: weight transpose + fp16 convert
    prep_weight<<<dim3((kM0+31)/32, (kM0+31)/32), 256>>>(w1, w1tv, kM0, kM0);
    prep_weight<<<dim3((kG +31)/32, (kM0+31)/32), 256>>>(w2, w2tv, kM0, kG);

    // stage 1: features (fp16 f0 + fp32 f1/f1e/f2)
    build_features<<<kN, 256>>>(xs, xv);

    // stage 2: h = fp16(silu(f0h @ W1))      [8192 x 2672]
    {
        dim3 grid((kM0 + 127)/128, kN/128);
        hmma_gemm<true><<<grid, 256, kHGemmSmem>>>(f0hv, w1tv, nullptr, hv, kM0, kM0);
    }
    // stage 3: g = h @ W2 (fp32)             [8192 x 5776]
    {
        dim3 grid((kG + 127)/128, kN/128);
        hmma_gemm<false><<<grid, 256, kHGemmSmem>>>(hv, w2tv, gv, nullptr, kM0, kG);
    }

    // stage 5: all gated output GEMMs in one launch (tf32 MMA)
    skinny_all<<<832, 256>>>(gv, w0, w1o, w1e, w2e, out);
}

// round 17
// speedup vs baseline: 1.5835x; 1.0909x over previous
#include <cuda_runtime.h>
#include <cuda_fp16.h>
#include <cstdint>
#include <math.h>

// ---------------- problem constants ----------------
constexpr int kN    = 8192;
constexpr int kC0   = 64;
constexpr int kC1   = 32;
constexpr int kP0   = kC0*(kC0+1)/2;      // 2080
constexpr int kP1   = kC1*(kC1+1)/2;      // 528
constexpr int kA1   = kC1*(kC1-1)/2;      // 496
constexpr int kM0   = kC0 + kP0 + kP1;    // 2672
constexpr int kM1   = kC1 + kC0*kC1;      // 2080
constexpr int kG    = kM0 + kM1 + kA1 + kP1; // 5776
constexpr int kOUTW = 64 + 32*3 + 16*3 + 16*5; // 288

__device__ constexpr float kRS2 = 0.70710678118654752f;
__device__ constexpr float kRS3 = 0.57735026918962576f;
__device__ constexpr float kS6  = 0.40824829046386302f;

// ---------------- scratch (static device globals; no allocation) ----------------
__device__ float  d_f0t[(size_t)kN*kM0];   // fp32 (skinny path)
__device__ __half d_f0h[(size_t)kN*kM0];   // fp16 (GEMM1 A)
__device__ __half d_h  [(size_t)kN*kM0];   // fp16 silu output (GEMM2 A)
__device__ float  d_g  [(size_t)kN*kG];    // fp32 gates
__device__ float  d_f1 [3][(size_t)kN*kM1];
__device__ float  d_f1e[3][(size_t)kN*kA1];
__device__ float  d_f2 [5][(size_t)kN*kP1];
__device__ __half d_w1t[(size_t)kM0*kM0];  // [N][K] K-major fp16
__device__ __half d_w2t[(size_t)kG*kM0];
__device__ int2   t_iu0[kP0];
__device__ float  t_c0 [kP0];
__device__ int2   t_iu1[kP1];
__device__ float  t_c1 [kP1];
__device__ int2   t_il [kA1];

// ---------------- PTX helpers ----------------
__device__ __forceinline__ uint32_t smem_u32(const void* p) {
    uint32_t a;
    asm("{ .reg .u64 t; cvta.to.shared.u64 t, %1; cvt.u32.u64 %0, t; }" : "=r"(a) : "l"(p));
    return a;
}
__device__ __forceinline__ void cp16(uint32_t dst, const void* src, bool pred) {
    int sz = pred ? 16 : 0;
    asm volatile("cp.async.cg.shared.global [%0], [%1], 16, %2;"
                 :: "r"(dst), "l"(src), "r"(sz) : "memory");
}
__device__ __forceinline__ void cp_commit() {
    asm volatile("cp.async.commit_group;" ::: "memory");
}
template<int NG>
__device__ __forceinline__ void cp_wait() {
    asm volatile("cp.async.wait_group %0;" :: "n"(NG) : "memory");
}
__device__ __forceinline__ void ldm_x4(uint32_t* r, uint32_t addr) {
    asm volatile("ldmatrix.sync.aligned.m8n8.x4.shared.b16 {%0,%1,%2,%3}, [%4];"
                 : "=r"(r[0]), "=r"(r[1]), "=r"(r[2]), "=r"(r[3]) : "r"(addr));
}
__device__ __forceinline__ void mma_f16(float* c, const uint32_t* a, const uint32_t* b) {
    asm volatile("mma.sync.aligned.m16n8k16.row.col.f32.f16.f16.f32 "
                 "{%0,%1,%2,%3}, {%4,%5,%6,%7}, {%8,%9}, {%0,%1,%2,%3};"
                 : "+f"(c[0]), "+f"(c[1]), "+f"(c[2]), "+f"(c[3])
                 : "r"(a[0]), "r"(a[1]), "r"(a[2]), "r"(a[3]), "r"(b[0]), "r"(b[1]));
}
__device__ __forceinline__ void mma_tf32(float* c, const uint32_t* a, const uint32_t* b) {
    asm volatile("mma.sync.aligned.m16n8k8.row.col.f32.tf32.tf32.f32 "
                 "{%0,%1,%2,%3}, {%4,%5,%6,%7}, {%8,%9}, {%0,%1,%2,%3};"
                 : "+f"(c[0]), "+f"(c[1]), "+f"(c[2]), "+f"(c[3])
                 : "r"(a[0]), "r"(a[1]), "r"(a[2]), "r"(a[3]), "r"(b[0]), "r"(b[1]));
}
__device__ __forceinline__ float tf32_round(float x) {
    uint32_t u;
    asm("cvt.rna.tf32.f32 %0, %1;" : "=r"(u) : "f"(x));
    return __uint_as_float(u);
}

// ---------------- triu decode (table init only) ----------------
__device__ __forceinline__ int2 triu_decode(int p, int C, int k)
{
    int Cm = C - k;
    float t = 2.0f*Cm + 1.0f;
    int a = (int)((t - sqrtf(t*t - 8.0f*(float)p)) * 0.5f);
    if (a < 0) a = 0;
    if (a > Cm-1) a = Cm-1;
    while (a > 0 && a*Cm - (a*(a-1))/2 > p) --a;
    while ((a+1)*Cm - ((a+1)*a)/2 <= p) ++a;
    int b = a + k + (p - (a*Cm - (a*(a-1))/2));
    return make_int2(a, b);
}

__global__ __launch_bounds__(256)
void init_tables()
{
    int i = blockIdx.x*256 + threadIdx.x;
    if (i < kP0) {
        int2 ab = triu_decode(i, kC0, 0);
        t_iu0[i] = ab;
        t_c0[i]  = (ab.x == ab.y) ? kRS2 : 1.0f;
    }
    if (i < kP1) {
        int2 ab = triu_decode(i, kC1, 0);
        t_iu1[i] = ab;
        t_c1[i]  = (ab.x == ab.y) ? kRS2 : 1.0f;
    }
    if (i < kA1) t_il[i] = triu_decode(i, kC1, 1);
}

// ---------------- stage 0: weight transpose + fp16 convert ----------------
__global__ __launch_bounds__(256)
void prep_weight(const float* __restrict__ W, __half* __restrict__ T, int K, int N)
{
    __shared__ float tile[32][33];
    int kb = blockIdx.y*32, nb = blockIdx.x*32;
    int tx = threadIdx.x & 31, ty = threadIdx.x >> 5;
    for (int i = ty; i < 32; i += 8) {
        int k = kb + i, n = nb + tx;
        tile[i][tx] = (k < K && n < N) ? W[(size_t)k*N + n] : 0.f;
    }
    __syncthreads();
    for (int i = ty; i < 32; i += 8) {
        int n = nb + i, k = kb + tx;
        if (n < N && k < K)
            T[(size_t)n*K + k] = __float2half(tile[tx][i]);
    }
}

// ---------------- stage 1: feature construction (table-driven) ----------------
__global__ __launch_bounds__(256)
void build_features(const float* __restrict__ xs, const float* __restrict__ xv)
{
    const int n = blockIdx.x;
    __shared__ float s[kC0];
    __shared__ float v[kC1][3];
    const int t = threadIdx.x;
    if (t < kC0) s[t] = xs[(size_t)n*kC0 + t];
    if (t >= 128 && t < 128 + kC1*3) ((float*)v)[t-128] = xv[(size_t)n*kC1*3 + (t-128)];
    __syncthreads();

    float*  f0t = d_f0t + (size_t)n*kM0;
    __half* f0h = d_f0h + (size_t)n*kM0;

    if (t < kC0) { float x = s[t]; f0t[t] = x; f0h[t] = __float2half(x); }
    for (int p = t; p < kP0; p += 256) {
        int2 ab = t_iu0[p];
        float x = s[ab.x]*s[ab.y]*t_c0[p];
        f0t[kC0 + p] = x;
        f0h[kC0 + p] = __float2half(x);
    }
    for (int p = t; p < kP1; p += 256) {
        int2 ab = t_iu1[p];
        float x = (v[ab.x][0]*v[ab.y][0] + v[ab.x][1]*v[ab.y][1] + v[ab.x][2]*v[ab.y][2])
                * t_c1[p] * kRS3;
        f0t[kC0 + kP0 + p] = x;
        f0h[kC0 + kP0 + p] = __float2half(x);
    }
    for (int c = t; c < kM1; c += 256) {
        float e0, e1, e2;
        if (c < kC1) { e0 = v[c][0]; e1 = v[c][1]; e2 = v[c][2]; }
        else {
            int cc = (c - kC1) >> 5;
            int vv = (c - kC1) & 31;
            float sc = s[cc];
            e0 = sc*v[vv][0]; e1 = sc*v[vv][1]; e2 = sc*v[vv][2];
        }
        size_t idx = (size_t)n*kM1 + c;
        d_f1[0][idx] = e0; d_f1[1][idx] = e1; d_f1[2][idx] = e2;
    }
    for (int p = t; p < kA1; p += 256) {
        int2 ab = t_il[p];
        float ux = v[ab.x][0], uy = v[ab.x][1], uz = v[ab.x][2];
        float wx = v[ab.y][0], wy = v[ab.y][1], wz = v[ab.y][2];
        size_t idx = (size_t)n*kA1 + p;
        d_f1e[0][idx] = (uy*wz - uz*wy) * kRS2;
        d_f1e[1][idx] = (uz*wx - ux*wz) * kRS2;
        d_f1e[2][idx] = (ux*wy - uy*wx) * kRS2;
    }
    for (int p = t; p < kP1; p += 256) {
        int2 ab = t_iu1[p];
        float c = t_c1[p];
        float ax = v[ab.x][0], ay = v[ab.x][1], az = v[ab.x][2];
        float bx = v[ab.y][0], by = v[ab.y][1], bz = v[ab.y][2];
        size_t idx = (size_t)n*kP1 + p;
        d_f2[0][idx] = kRS2*(ax*by + ay*bx)*c;
        d_f2[1][idx] = kRS2*(ay*bz + az*by)*c;
        d_f2[2][idx] = kRS2*(ax*bz + az*bx)*c;
        d_f2[3][idx] = kRS2*(ax*bx - ay*by)*c;
        d_f2[4][idx] = kS6*(-ax*bx - ay*by + 2.0f*az*bz)*c;
    }
}

// ---- fp16 HMMA GEMM: 128x128 tile, 256 thr, 2 CTAs/SM, BK=32 halves, 4-stage ----
constexpr int kHRowStride  = 80;                    // 64B data + 16B pad
constexpr int kHTileBytes  = 128 * kHRowStride;     // 10240
constexpr int kHBufBytes   = 2 * kHTileBytes;       // 20480
constexpr int kHStages     = 4;
constexpr int kHGemmSmem   = kHStages * kHBufBytes; // 81920

template<bool SILU>
__global__ __launch_bounds__(256, 2)
void hmma_gemm(const __half* __restrict__ A, const __half* __restrict__ B,
               float* __restrict__ Cf, __half* __restrict__ Ch, int K, int Nglob)
{
    extern __shared__ char smem[];
    const uint32_t sbase = smem_u32(smem);
    const int tid  = threadIdx.x;
    const int wid  = tid >> 5, lane = tid & 31;
    const int m0   = blockIdx.y * 128;
    const int n0   = blockIdx.x * 128;
    const int wm   = (wid & 1) * 64;
    const int wn   = (wid >> 1) * 32;

    float acc[4][4][4];
    #pragma unroll
    for (int i = 0; i < 4; i++)
        #pragma unroll
        for (int j = 0; j < 4; j++)
            #pragma unroll
            for (int q = 0; q < 4; q++) acc[i][j][q] = 0.0f;

    const int nChunks = (K + 31) / 32;

    auto load_chunk = [&](int c) {
        const uint32_t db = sbase + (uint32_t)(c % kHStages) * kHBufBytes;
        const int k0 = c * 32;
        #pragma unroll
        for (int t = 0; t < 4; t++) {
            int idx = t * 256 + tid;
            int kc  = idx & 3;
            int gk  = k0 + kc * 8;
            bool kok = gk < K;
            int row = (idx >> 2) & 127;
            const __half* src;
            uint32_t dst;
            bool ok;
            if (idx < 512) {
                dst = db + (uint32_t)row * kHRowStride + kc * 16;
                src = A + (size_t)(m0 + row) * K + (kok ? gk : 0);
                ok  = kok;
            } else {
                dst = db + (uint32_t)kHTileBytes + (uint32_t)row * kHRowStride + kc * 16;
                int gn = n0 + row;
                bool nok = gn < Nglob;
                src = B + (size_t)(nok ? gn : 0) * K + (kok ? gk : 0);
                ok  = kok && nok;
            }
            cp16(dst, src, ok);
        }
        cp_commit();
    };

    // prologue: 3 chunks in flight
    load_chunk(0);
    if (nChunks > 1) load_chunk(1);
    if (nChunks > 2) load_chunk(2);

    for (int c = 0; c < nChunks; c++) {
        // ladder: guarantee chunk c resident (allow min(2, remaining) newer groups)
        if (c + 2 < nChunks)      cp_wait<2>();
        else if (c + 1 < nChunks) cp_wait<1>();
        else                      cp_wait<0>();
        __syncthreads();
        // buffer (c+3)%4 == (c-1)%4: its compute finished before this barrier
        if (c + 3 < nChunks) load_chunk(c + 3);

        const uint32_t db = sbase + (uint32_t)(c % kHStages) * kHBufBytes;
        const uint32_t aT = db;
        const uint32_t bT = db + kHTileBytes;

        #pragma unroll
        for (int ks = 0; ks < 2; ks++) {
            uint32_t af[4][4], bf[4][2];
            const int arow = wm + (lane & 15);
            const int acol = ks * 32 + (lane >> 4) * 16;
            #pragma unroll
            for (int mt = 0; mt < 4; mt++) {
                uint32_t off = (uint32_t)(arow + mt*16) * kHRowStride + acol;
                ldm_x4(af[mt], aT + off);
            }
            const int bg  = lane >> 3;
            const int br  = lane & 7;
            const int bnt = bg >> 1;
            const int bkh = (bg & 1) * 16;
            #pragma unroll
            for (int np = 0; np < 2; np++) {
                uint32_t off = (uint32_t)(wn + (np*2 + bnt)*8 + br) * kHRowStride
                             + ks*32 + bkh;
                ldm_x4(&bf[np*2][0], bT + off);
            }
            #pragma unroll
            for (int mt = 0; mt < 4; mt++)
                #pragma unroll
                for (int nt = 0; nt < 4; nt++)
                    mma_f16(acc[mt][nt], af[mt], bf[nt]);
        }
    }

    #pragma unroll
    for (int mt = 0; mt < 4; mt++) {
        #pragma unroll
        for (int nt = 0; nt < 4; nt++) {
            int row = m0 + wm + mt*16 + (lane >> 2);
            int col = n0 + wn + nt*8 + (lane & 3) * 2;
            #pragma unroll
            for (int half = 0; half < 2; half++) {
                int r = row + half * 8;
                float v0 = acc[mt][nt][half*2 + 0];
                float v1 = acc[mt][nt][half*2 + 1];
                if (col < Nglob) {
                    size_t o = (size_t)r * Nglob + col;
                    if (SILU) {
                        v0 = v0 / (1.0f + __expf(-v0));
                        v1 = v1 / (1.0f + __expf(-v1));
                        Ch[o]   = __float2half(v0);
                        Ch[o+1] = __float2half(v1);
                    } else {
                        Cf[o]   = v0;
                        Cf[o+1] = v1;
                    }
                }
            }
        }
    }
}

// ---- stage 5: ALL output families in ONE launch (tf32 MMA, fp32 g — R14-proven) ----
constexpr int kSkRowStride = 144;
constexpr int kSkASize     = 128 * kSkRowStride;    // 18432
constexpr int kSkBSize     = 32  * kSkRowStride;    // 4608
constexpr int kSkBuf       = kSkASize + kSkBSize;   // 23040

__global__ __launch_bounds__(256)
void skinny_all(const float* __restrict__ g,
                const float* __restrict__ w0,  const float* __restrict__ w1o,
                const float* __restrict__ w1e, const float* __restrict__ w2e,
                float* __restrict__ out)
{
    __shared__ char smem[2 * kSkBuf];
    const int tid  = threadIdx.x;
    const int wid  = tid >> 5, lane = tid & 31;
    const int b    = blockIdx.x;

    const float* A; const float* Wp;
    int K, gOff, ldw, colOff = 0, outBase, outStride, comp = 0, OC, rb;
    if (b < 128) {
        rb = b & 63; colOff = (b >> 6) * 32;
        A = d_f0t; K = kM0; gOff = 0; Wp = w0; ldw = 64;
        outBase = 0; outStride = 1; OC = 32;
    } else if (b < 320) {
        int t = b - 128; comp = t >> 6; rb = t & 63;
        A = d_f1[comp]; K = kM1; gOff = kM0; Wp = w1o; ldw = 32;
        outBase = 64; outStride = 3; OC = 32;
    } else if (b < 512) {
        int t = b - 320; comp = t >> 6; rb = t & 63;
        A = d_f1e[comp]; K = kA1; gOff = kM0 + kM1; Wp = w1e; ldw = 16;
        outBase = 160; outStride = 3; OC = 16;
    } else {
        int t = b - 512; comp = t >> 6; rb = t & 63;
        A = d_f2[comp]; K = kP1; gOff = kM0 + kM1 + kA1; Wp = w2e; ldw = 16;
        outBase = 208; outStride = 5; OC = 16;
    }
    const int n0 = rb * 128;
    const int wm = wid * 16;
    const int ocDiv8  = OC >> 3;
    const int ocDiv16 = OC >> 4;

    float acc[4][4];
    #pragma unroll
    for (int j = 0; j < 4; j++)
        #pragma unroll
        for (int q = 0; q < 4; q++) acc[j][q] = 0.0f;

    const int nChunks = (K + 31) / 32;

    float4 aP[4], gP[4];
    float  wP[4];

    auto load_regs = [&](int c) {
        const int k0 = c * 32;
        #pragma unroll
        for (int j = 0; j < 4; j++) {
            int i  = j * 256 + tid;
            int r  = i >> 3;
            int kq = i & 7;
            int gk = k0 + kq * 4;
            if (gk < K) {
                aP[j] = *reinterpret_cast<const float4*>(A + (size_t)(n0 + r)*K + gk);
                gP[j] = *reinterpret_cast<const float4*>(g + (size_t)(n0 + r)*kG + gOff + gk);
            } else {
                aP[j] = make_float4(0.f, 0.f, 0.f, 0.f);
                gP[j] = make_float4(1.f, 1.f, 1.f, 1.f);
            }
        }
        #pragma unroll
        for (int j = 0; j < 4; j++) {
            int i = j * 256 + tid;
            wP[j] = 0.f;
            if (i < OC * 32) {
                int k = i / OC, o = i % OC;
                if (k0 + k < K)
                    wP[j] = Wp[(size_t)(k0 + k)*ldw + colOff + o];
            }
        }
    };

    auto store_smem = [&](int buf) {
        char* base = smem + buf * kSkBuf;
        #pragma unroll
        for (int j = 0; j < 4; j++) {
            int i  = j * 256 + tid;
            int r  = i >> 3;
            int kq = i & 7;
            float4 a4;
            a4.x = tf32_round(aP[j].x * gP[j].x);
            a4.y = tf32_round(aP[j].y * gP[j].y);
            a4.z = tf32_round(aP[j].z * gP[j].z);
            a4.w = tf32_round(aP[j].w * gP[j].w);
            *reinterpret_cast<float4*>(base + r*kSkRowStride + kq*16) = a4;
        }
        #pragma unroll
        for (int j = 0; j < 4; j++) {
            int i = j * 256 + tid;
            if (i < OC * 32) {
                int k = i / OC, o = i % OC;
                *reinterpret_cast<float*>(base + kSkASize + o*kSkRowStride + k*4) = wP[j];
            }
        }
    };

    load_regs(0);

    for (int c = 0; c < nChunks; c++) {
        const int buf = c & 1;
        store_smem(buf);
        __syncthreads();
        if (c + 1 < nChunks) load_regs(c + 1);

        const uint32_t aT = smem_u32(smem) + buf * kSkBuf;
        const uint32_t bT = aT + kSkASize;

        #pragma unroll
        for (int s = 0; s < 4; s++) {
            uint32_t af[4], bf[4][2];
            const int arow = wm + (lane & 15);
            const int acol = s * 32 + (lane >> 4) * 16;
            ldm_x4(af, aT + (uint32_t)arow * kSkRowStride + acol);
            const int bg  = lane >> 3;
            const int br  = lane & 7;
            const int bnt = bg >> 1;
            const int bkh = (bg & 1) * 16;
            #pragma unroll
            for (int np = 0; np < 2; np++) {
                if (np < ocDiv16) {
                    uint32_t off = (uint32_t)((np*2 + bnt)*8 + br) * kSkRowStride
                                 + s*32 + bkh;
                    ldm_x4(&bf[np*2][0], bT + off);
                }
            }
            #pragma unroll
            for (int nt = 0; nt < 4; nt++)
                if (nt < ocDiv8)
                    mma_tf32(acc[nt], af, bf[nt]);
        }
    }

    #pragma unroll
    for (int nt = 0; nt < 4; nt++) {
        if (nt < ocDiv8) {
            int row = n0 + wm + (lane >> 2);
            int oc  = colOff + nt*8 + (lane & 3) * 2;
            #pragma unroll
            for (int half = 0; half < 2; half++) {
                int r = row + half * 8;
                size_t o = (size_t)r * kOUTW + outBase + comp + (size_t)oc * outStride;
                out[o]             = acc[nt][half*2 + 0];
                out[o + outStride] = acc[nt][half*2 + 1];
            }
        }
    }
}

// ---------------- launch ----------------
extern "C" void kernel_launch(void* const* d_in, const int* in_sizes, int n_in,
                              void* d_out, int out_size)
{
    const float* xs  = (const float*)d_in[0];
    const float* xv  = (const float*)d_in[1];
    const float* w1  = (const float*)d_in[2];
    const float* w2  = (const float*)d_in[3];
    const float* w0  = (const float*)d_in[4];
    const float* w1o = (const float*)d_in[5];
    const float* w1e = (const float*)d_in[6];
    const float* w2e = (const float*)d_in[7];
    float* out = (float*)d_out;

    void *pf0h, *ph, *pg, *pw1t, *pw2t;
    cudaGetSymbolAddress(&pf0h, d_f0h);
    cudaGetSymbolAddress(&ph,   d_h);
    cudaGetSymbolAddress(&pg,   d_g);
    cudaGetSymbolAddress(&pw1t, d_w1t);
    cudaGetSymbolAddress(&pw2t, d_w2t);

    __half* f0hv = (__half*)pf0h;
    __half* hv   = (__half*)ph;
    float*  gv   = (float*)pg;
    __half* w1tv = (__half*)pw1t;
    __half* w2tv = (__half*)pw2t;

    cudaFuncSetAttribute(hmma_gemm<true>,  cudaFuncAttributeMaxDynamicSharedMemorySize, kHGemmSmem);
    cudaFuncSetAttribute(hmma_gemm<false>, cudaFuncAttributeMaxDynamicSharedMemorySize, kHGemmSmem);

    // stage -1: pair tables
    init_tables<<<(kP0 + 255)/256, 256>>>();

    // stage 0: weight transpose + fp16 convert
    prep_weight<<<dim3((kM0+31)/32, (kM0+31)/32), 256>>>(w1, w1tv, kM0, kM0);
    prep_weight<<<dim3((kG +31)/32, (kM0+31)/32), 256>>>(w2, w2tv, kM0, kG);

    // stage 1: features (fp32 f0t + fp16 f0h)
    build_features<<<kN, 256>>>(xs, xv);

    // stage 2: h = fp16(silu(f0h @ W1))      [8192 x 2672]
    {
        dim3 grid((kM0 + 127)/128, kN/128);
        hmma_gemm<true><<<grid, 256, kHGemmSmem>>>(f0hv, w1tv, nullptr, hv, kM0, kM0);
    }
    // stage 3: g = h @ W2 (fp32)             [8192 x 5776]
    {
        dim3 grid((kG + 127)/128, kN/128);
        hmma_gemm<false><<<grid, 256, kHGemmSmem>>>(hv, w2tv, gv, nullptr, kM0, kG);
    }

    // stage 5: all gated output GEMMs in one launch (tf32 MMA)
    skinny_all<<<832, 256>>>(gv, w0, w1o, w1e, w2e, out);
}